// round 7
// baseline (speedup 1.0000x reference)
#include <cuda_runtime.h>
#include <cstdint>

// Problem constants
#define B_   8
#define N1_  8192
#define N2_  2048
#define C1_  128
#define C2_  256
#define H_   256
#define CIN_ 384   // C2 + C1

typedef unsigned long long u64;

// ---------------- device scratch (no allocations allowed) ----------------
__device__ float  g_feat2t[B_ * N2_ * C2_];     // [B][N2][C2] fp32
__device__ float4 g_x2p[B_ * N2_];              // packed {x,y,z,|x|^2}
__device__ int    g_idx[B_ * N1_ * 3];
__device__ float  g_w  [B_ * N1_ * 3];
__device__ float  g_pd [B_ * N1_ * 4 * 3];      // partial top-3 dists (4 quarters)
__device__ int    g_pi [B_ * N1_ * 4 * 3];      // partial top-3 indices
__device__ float  g_xcat[B_ * N1_ * CIN_];      // [B][N1][384] tf32-rounded
__device__ float  g_A1[H_ * CIN_];              // tf32-rounded folded weights
__device__ float  g_c1[H_];
__device__ float  g_A2[H_ * H_];
__device__ float  g_c2[H_];

// ---------------- small PTX helpers ----------------------------------------
__device__ __forceinline__ float to_tf32(float x) {
    unsigned u;
    asm("cvt.rna.tf32.f32 %0, %1;" : "=r"(u) : "f"(x));
    return __uint_as_float(u);
}
__device__ __forceinline__ uint32_t smem_u32(const void* p) {
    uint32_t a;
    asm("{ .reg .u64 t; cvta.to.shared.u64 t, %1; cvt.u32.u64 %0, t; }" : "=r"(a) : "l"(p));
    return a;
}
__device__ __forceinline__ void cpa16(uint32_t dst, const float* src) {
    asm volatile("cp.async.cg.shared.global [%0], [%1], 16;" :: "r"(dst), "l"(src));
}
#define CP_COMMIT()  asm volatile("cp.async.commit_group;")
#define CP_WAIT1()   asm volatile("cp.async.wait_group 1;")
#define CP_WAIT0()   asm volatile("cp.async.wait_group 0;")

// m16n8k8 tf32 MMA, D = A*B + D
__device__ __forceinline__ void mma_tf32(float* c, const uint32_t* a,
                                         uint32_t b0, uint32_t b1) {
    asm volatile(
        "mma.sync.aligned.m16n8k8.row.col.f32.tf32.tf32.f32 "
        "{%0,%1,%2,%3}, {%4,%5,%6,%7}, {%8,%9}, {%0,%1,%2,%3};"
        : "+f"(c[0]), "+f"(c[1]), "+f"(c[2]), "+f"(c[3])
        : "r"(a[0]), "r"(a[1]), "r"(a[2]), "r"(a[3]), "r"(b0), "r"(b1));
}

// ---------------- 1) transpose features2 [B][C2][N2] -> [B][N2][C2] --------
__global__ void transpose_f2_kernel(const float* __restrict__ f2) {
    __shared__ float tile[32][33];
    int b  = blockIdx.z;
    int c0 = blockIdx.y * 32;
    int n0 = blockIdx.x * 32;
    int tx = threadIdx.x, ty = threadIdx.y;
    const float* src = f2 + (size_t)b * C2_ * N2_;
#pragma unroll
    for (int i = 0; i < 32; i += 8)
        tile[ty + i][tx] = src[(size_t)(c0 + ty + i) * N2_ + n0 + tx];
    __syncthreads();
    float* dst = g_feat2t + (size_t)b * N2_ * C2_;
#pragma unroll
    for (int i = 0; i < 32; i += 8)
        dst[(size_t)(n0 + ty + i) * C2_ + c0 + tx] = tile[tx][ty + i];
}

// ---------------- 2) setup: pack xyz2 + fold BN into weights ---------------
__global__ void setup_kernel(const float* __restrict__ xyz2,
                             const float* __restrict__ w1, const float* __restrict__ b1,
                             const float* __restrict__ g1, const float* __restrict__ be1,
                             const float* __restrict__ m1, const float* __restrict__ v1,
                             const float* __restrict__ w2, const float* __restrict__ b2,
                             const float* __restrict__ g2, const float* __restrict__ be2,
                             const float* __restrict__ m2, const float* __restrict__ v2) {
    int blk = blockIdx.x;
    int t = threadIdx.x;
    if (blk < 64) {                       // pack xyz2
        int b = blk >> 3;
        int i = (blk & 7) * 256 + t;
        const float* x2 = xyz2 + (size_t)b * 3 * N2_;
        float X = x2[i], Y = x2[N2_ + i], Z = x2[2 * N2_ + i];
        g_x2p[b * N2_ + i] = make_float4(X, Y, Z, X * X + Y * Y + Z * Z);
    } else {                              // fold BN (32 blocks, 8192 threads)
        int tid2 = (blk - 64) * 256 + t;
        if (tid2 < H_) {
            float s1 = g1[tid2] * rsqrtf(v1[tid2] + 1e-5f);
            g_c1[tid2] = (b1[tid2] - m1[tid2]) * s1 + be1[tid2];
            float s2 = g2[tid2] * rsqrtf(v2[tid2] + 1e-5f);
            g_c2[tid2] = (b2[tid2] - m2[tid2]) * s2 + be2[tid2];
        }
        for (int j = tid2; j < H_ * CIN_; j += 8192) {
            int o = j / CIN_;
            float s = g1[o] * rsqrtf(v1[o] + 1e-5f);
            g_A1[j] = to_tf32(w1[j] * s);
        }
        for (int j = tid2; j < H_ * H_; j += 8192) {
            int o = j / H_;
            float s = g2[o] * rsqrtf(v2[o] + 1e-5f);
            g_A2[j] = to_tf32(w2[j] * s);
        }
    }
}

// ---------------- 3) kNN partial: quarter of N2, 2 points/thread -----------
#define QN_ (N2_ / 4)   // 512
__global__ void __launch_bounds__(128)
knn_part_kernel(const float* __restrict__ xyz1) {
    __shared__ float4 s2[QN_];
    int b  = blockIdx.z;
    int q  = blockIdx.y;
    int n0 = blockIdx.x * 256;
    int t  = threadIdx.x;

    const float4* src = g_x2p + b * N2_ + q * QN_;
    for (int i = t; i < QN_; i += 128) s2[i] = src[i];
    __syncthreads();

    const float* x1 = xyz1 + (size_t)b * 3 * N1_;
    int na = n0 + t, nb = n0 + 128 + t;
    float ax = x1[na], ay = x1[N1_ + na], az = x1[2 * N1_ + na];
    float bx = x1[nb], by = x1[N1_ + nb], bz = x1[2 * N1_ + nb];

    float ad0 = 3.4e38f, ad1 = 3.4e38f, ad2 = 3.4e38f;
    float bd0 = 3.4e38f, bd1 = 3.4e38f, bd2 = 3.4e38f;
    int ai0 = 0, ai1 = 0, ai2 = 0, bi0 = 0, bi1 = 0, bi2 = 0;

#pragma unroll 4
    for (int j = 0; j < QN_; j++) {
        float4 p = s2[j];
        float ta = ax * p.x; ta = fmaf(ay, p.y, ta); ta = fmaf(az, p.z, ta);
        float da = fmaf(-2.0f, ta, p.w);
        float tb = bx * p.x; tb = fmaf(by, p.y, tb); tb = fmaf(bz, p.z, tb);
        float db = fmaf(-2.0f, tb, p.w);
        if (da < ad2) {
            if (da < ad1) {
                if (da < ad0) { ad2 = ad1; ai2 = ai1; ad1 = ad0; ai1 = ai0; ad0 = da; ai0 = j; }
                else          { ad2 = ad1; ai2 = ai1; ad1 = da;  ai1 = j; }
            } else            { ad2 = da;  ai2 = j; }
        }
        if (db < bd2) {
            if (db < bd1) {
                if (db < bd0) { bd2 = bd1; bi2 = bi1; bd1 = bd0; bi1 = bi0; bd0 = db; bi0 = j; }
                else          { bd2 = bd1; bi2 = bi1; bd1 = db;  bi1 = j; }
            } else            { bd2 = db;  bi2 = j; }
        }
    }
    int joff = q * QN_;
    size_t basea = ((size_t)(b * N1_ + na) * 4 + q) * 3;
    g_pd[basea + 0] = ad0; g_pd[basea + 1] = ad1; g_pd[basea + 2] = ad2;
    g_pi[basea + 0] = ai0 + joff; g_pi[basea + 1] = ai1 + joff; g_pi[basea + 2] = ai2 + joff;
    size_t baseb = ((size_t)(b * N1_ + nb) * 4 + q) * 3;
    g_pd[baseb + 0] = bd0; g_pd[baseb + 1] = bd1; g_pd[baseb + 2] = bd2;
    g_pi[baseb + 0] = bi0 + joff; g_pi[baseb + 1] = bi1 + joff; g_pi[baseb + 2] = bi2 + joff;
}

// ---------------- 4) merge 4 partial top-3 lists + weights -----------------
__global__ void knn_merge_kernel(const float* __restrict__ xyz1) {
    int gid = blockIdx.x * 256 + threadIdx.x;   // 0 .. B*N1-1
    int b = gid >> 13;
    int n = gid & (N1_ - 1);

    float d0 = 3.4e38f, d1 = 3.4e38f, d2 = 3.4e38f;
    int   i0 = 0, i1 = 0, i2 = 0;
    size_t base = (size_t)gid * 12;
#pragma unroll
    for (int k = 0; k < 12; k++) {
        float d = g_pd[base + k];
        int   i = g_pi[base + k];
        if (d < d2) {
            if (d < d1) {
                if (d < d0) { d2 = d1; i2 = i1; d1 = d0; i1 = i0; d0 = d; i0 = i; }
                else        { d2 = d1; i2 = i1; d1 = d;  i1 = i; }
            } else          { d2 = d;  i2 = i; }
        }
    }
    const float* x1 = xyz1 + (size_t)b * 3 * N1_;
    float px = x1[n], py = x1[N1_ + n], pz = x1[2 * N1_ + n];
    float pn = px * px + py * py + pz * pz;
    d0 = fmaxf(d0 + pn, 1e-10f);
    d1 = fmaxf(d1 + pn, 1e-10f);
    d2 = fmaxf(d2 + pn, 1e-10f);
    float w0 = 1.0f / d0, w1 = 1.0f / d1, w2 = 1.0f / d2;
    float inv = 1.0f / (w0 + w1 + w2);
    size_t ob = (size_t)gid * 3;
    g_idx[ob + 0] = i0; g_idx[ob + 1] = i1; g_idx[ob + 2] = i2;
    g_w[ob + 0] = w0 * inv; g_w[ob + 1] = w1 * inv; g_w[ob + 2] = w2 * inv;
}

// ---------------- 5) interp (ch 0..255) + skip transpose (ch 256..383) -----
__global__ void interp_skip_kernel(const float* __restrict__ f1) {
    __shared__ int   sidx[16 * 3];
    __shared__ float swt [16 * 3];
    __shared__ float tile[32][33];
    int blk = blockIdx.x;
    int t = threadIdx.x;
    if (blk < 4096) {
        // interp: 16 points per block, thread = channel
        int b  = blk >> 9;
        int n0 = (blk & 511) * 16;
        if (t < 48) {
            size_t base = ((size_t)(b * N1_ + n0)) * 3;
            sidx[t] = g_idx[base + t];
            swt[t]  = g_w[base + t];
        }
        __syncthreads();
        const float* f2 = g_feat2t + (size_t)b * N2_ * C2_;
        float* xc = g_xcat + ((size_t)(b * N1_ + n0)) * CIN_ + t;
#pragma unroll 4
        for (int p = 0; p < 16; p++) {
            float acc = swt[p * 3 + 0] * f2[(size_t)sidx[p * 3 + 0] * C2_ + t]
                      + swt[p * 3 + 1] * f2[(size_t)sidx[p * 3 + 1] * C2_ + t]
                      + swt[p * 3 + 2] * f2[(size_t)sidx[p * 3 + 2] * C2_ + t];
            xc[(size_t)p * CIN_] = to_tf32(acc);
        }
    } else {
        // skip transpose: [C1][N1] -> xcat[...][256+c]
        int r  = blk - 4096;                 // 0 .. 8191
        int b  = r >> 10;
        int rem = r & 1023;
        int c0 = (rem >> 8) * 32;            // 0..3 -> 0..96
        int n0 = (rem & 255) * 32;
        int tx = t & 31, ty = t >> 5;
        const float* src = f1 + (size_t)b * C1_ * N1_;
#pragma unroll
        for (int i = 0; i < 32; i += 8)
            tile[ty + i][tx] = src[(size_t)(c0 + ty + i) * N1_ + n0 + tx];
        __syncthreads();
        float* dst = g_xcat + (size_t)b * N1_ * CIN_;
#pragma unroll
        for (int i = 0; i < 32; i += 8)
            dst[(size_t)(n0 + ty + i) * CIN_ + C2_ + c0 + tx] = to_tf32(tile[tx][ty + i]);
    }
}

// ---------------- 6) fused 2-layer MLP, 64x256 tile, 2 CTAs/SM -------------
// Block: 64 points x 256 out-channels, 256 threads (8 warps: 2M x 4N,
// warp tile 32x64). Phase 1: y = relu(W1.x+c1) -> SMEM yfrag (A-frag order).
// Phase 2: out = relu(W2.y+c2), A resident, W2 double-buffered.
// SMEM: 2 x 5120 (phase1 A+B bufs; phase2 reuses [0,8192) for W2) + 16384
// yfrag = 26624 floats = 104 KB -> 2 CTAs/SM.
#define P1_BUF_FLOATS 5120
#define YFRAG_OFF     10240          // floats
#define MLP_SMEM      106496

__global__ void __launch_bounds__(256, 2)
mlp_fused_kernel(float* __restrict__ out_final) {
    extern __shared__ float smem[];
    uint32_t sbase = smem_u32(smem);

    int tid  = threadIdx.x;
    int wid  = tid >> 5;
    int lane = tid & 31;
    int g    = lane >> 2;        // groupID 0..7
    int t4   = lane & 3;         // threadID_in_group

    int wm = wid & 1;            // 0..1  (M warps, 32 rows each)
    int wn = wid >> 1;           // 0..3  (N warps, 64 cols each)

    int bz = blockIdx.x >> 7;              // batch
    int m0 = (blockIdx.x & 127) * 64;      // point tile

    const float* Abase = g_xcat + ((size_t)(bz * N1_ + m0)) * CIN_;
    float* yf = smem + YFRAG_OFF;

    float acc[2][8][4] = {};

    // ---- phase-1 staging (A 64x16: 1 chunk/thread; B 256x16: 4 chunks) ----
#define STAGE1(buf, kt) do {                                                   \
    uint32_t dbase = sbase + (buf) * (P1_BUF_FLOATS * 4);                      \
    {                                                                          \
        int m = tid >> 2, c4 = tid & 3;                                        \
        int r = m & 15;                                                        \
        int off = (((m >> 4) * 2 + (c4 >> 1)) * 4 + 2 * (c4 & 1) + (r >> 3)) * 32 \
                  + (r & 7) * 4;                                               \
        cpa16(dbase + off * 4, Abase + (size_t)m * CIN_ + (kt) * 16 + c4 * 4); \
    }                                                                          \
    _Pragma("unroll")                                                          \
    for (int c = 0; c < 4; c++) {                                              \
        int id = tid + c * 256;                                                \
        int n = id >> 2, c4 = id & 3;                                          \
        int off = 1024 + (((n >> 3) * 2 + (c4 >> 1)) * 2 + (c4 & 1)) * 32      \
                  + (n & 7) * 4;                                               \
        cpa16(dbase + off * 4, g_A1 + (size_t)n * CIN_ + (kt) * 16 + c4 * 4);  \
    }                                                                          \
    CP_COMMIT();                                                               \
} while (0)

    // ---- phase-2 B staging (W2 fragments into reused low SMEM) ----
#define STAGE2B(buf, kt) do {                                                  \
    uint32_t dbase = sbase + (buf) * 16384;                                    \
    _Pragma("unroll")                                                          \
    for (int c = 0; c < 4; c++) {                                              \
        int id = tid + c * 256;                                                \
        int n = id >> 2, c4 = id & 3;                                          \
        int off = (((n >> 3) * 2 + (c4 >> 1)) * 2 + (c4 & 1)) * 32             \
                  + (n & 7) * 4;                                               \
        cpa16(dbase + off * 4, g_A2 + (size_t)n * H_ + (kt) * 16 + c4 * 4);    \
    }                                                                          \
    CP_COMMIT();                                                               \
} while (0)

    // ================= phase 1: K = 384 =================
    STAGE1(0, 0);
#pragma unroll 1
    for (int kt = 0; kt < CIN_ / 16; kt++) {
        int cur = kt & 1;
        if (kt + 1 < CIN_ / 16) { STAGE1(cur ^ 1, kt + 1); CP_WAIT1(); }
        else                    { CP_WAIT0(); }
        __syncthreads();
        const float* As = smem + cur * P1_BUF_FLOATS;
        const float* Bs = As + 1024;
#pragma unroll
        for (int ks = 0; ks < 2; ks++) {
            uint32_t a[2][4];
#pragma unroll
            for (int mi = 0; mi < 2; mi++) {
                const float* ap = As + (((wm * 2 + mi) * 2 + ks) * 4) * 32 + lane;
                a[mi][0] = __float_as_uint(ap[0]);
                a[mi][1] = __float_as_uint(ap[32]);
                a[mi][2] = __float_as_uint(ap[64]);
                a[mi][3] = __float_as_uint(ap[96]);
            }
#pragma unroll
            for (int ni = 0; ni < 8; ni++) {
                const float* bp = Bs + (((wn * 8 + ni) * 2 + ks) * 2) * 32 + lane;
                uint32_t b0 = __float_as_uint(bp[0]);
                uint32_t b1 = __float_as_uint(bp[32]);
#pragma unroll
                for (int mi = 0; mi < 2; mi++)
                    mma_tf32(acc[mi][ni], a[mi], b0, b1);
            }
        }
        __syncthreads();
    }

    // ---- epilogue 1: bias+relu+tf32 -> yfrag (phase-2 A-fragment order) ----
#pragma unroll
    for (int ni = 0; ni < 8; ni++) {
        int nb = wn * 64 + ni * 8 + 2 * t4;
        float bv0 = __ldg(&g_c1[nb]);
        float bv1 = __ldg(&g_c1[nb + 1]);
#pragma unroll
        for (int mi = 0; mi < 2; mi++) {
            int mt2 = wm * 2 + mi;
            int ksg = wn * 8 + ni;
#pragma unroll
            for (int j = 0; j < 4; j++) {
                float v = to_tf32(fmaxf(acc[mi][ni][j] + ((j & 1) ? bv1 : bv0), 0.0f));
                int reg = 2 * (t4 >> 1) + (j >> 1);
                int ln  = g * 4 + ((2 * t4 + (j & 1)) & 3);
                yf[((mt2 * 32 + ksg) * 4 + reg) * 32 + ln] = v;
            }
        }
    }

    // re-zero accumulators for phase 2
#pragma unroll
    for (int mi = 0; mi < 2; mi++)
#pragma unroll
        for (int ni = 0; ni < 8; ni++)
#pragma unroll
            for (int j = 0; j < 4; j++) acc[mi][ni][j] = 0.0f;

    STAGE2B(0, 0);
    __syncthreads();   // yfrag visible to all

    // ================= phase 2: K = 256 (A resident in SMEM) =================
#pragma unroll 1
    for (int kt = 0; kt < H_ / 16; kt++) {
        int cur = kt & 1;
        if (kt + 1 < H_ / 16) { STAGE2B(cur ^ 1, kt + 1); CP_WAIT1(); }
        else                  { CP_WAIT0(); }
        __syncthreads();
        const float* Bs = smem + cur * 4096;
#pragma unroll
        for (int ks = 0; ks < 2; ks++) {
            uint32_t a[2][4];
#pragma unroll
            for (int mi = 0; mi < 2; mi++) {
                const float* ap = yf + (((wm * 2 + mi) * 32 + kt * 2 + ks) * 4) * 32 + lane;
                a[mi][0] = __float_as_uint(ap[0]);
                a[mi][1] = __float_as_uint(ap[32]);
                a[mi][2] = __float_as_uint(ap[64]);
                a[mi][3] = __float_as_uint(ap[96]);
            }
#pragma unroll
            for (int ni = 0; ni < 8; ni++) {
                const float* bp = Bs + (((wn * 8 + ni) * 2 + ks) * 2) * 32 + lane;
                uint32_t b0 = __float_as_uint(bp[0]);
                uint32_t b1 = __float_as_uint(bp[32]);
#pragma unroll
                for (int mi = 0; mi < 2; mi++)
                    mma_tf32(acc[mi][ni], a[mi], b0, b1);
            }
        }
        __syncthreads();
    }

    // ---- epilogue 2: bias+relu -> out [B][H][N1] (coalesced along points) ----
    float* dst = out_final + (size_t)bz * H_ * N1_;
#pragma unroll
    for (int ni = 0; ni < 8; ni++) {
        int n = wn * 64 + ni * 8 + 2 * t4;
        float bv0 = __ldg(&g_c2[n]);
        float bv1 = __ldg(&g_c2[n + 1]);
#pragma unroll
        for (int mi = 0; mi < 2; mi++) {
            int m = m0 + wm * 32 + mi * 16 + g;
            float c0 = fmaxf(acc[mi][ni][0] + bv0, 0.0f);
            float c1 = fmaxf(acc[mi][ni][1] + bv1, 0.0f);
            float c2 = fmaxf(acc[mi][ni][2] + bv0, 0.0f);
            float c3 = fmaxf(acc[mi][ni][3] + bv1, 0.0f);
            dst[(size_t)n * N1_ + m]           = c0;
            dst[(size_t)(n + 1) * N1_ + m]     = c1;
            dst[(size_t)n * N1_ + m + 8]       = c2;
            dst[(size_t)(n + 1) * N1_ + m + 8] = c3;
        }
    }
}

// ---------------- launch ----------------------------------------------------
extern "C" void kernel_launch(void* const* d_in, const int* in_sizes, int n_in,
                              void* d_out, int out_size) {
    const float* xyz1      = (const float*)d_in[0];
    const float* xyz2      = (const float*)d_in[1];
    const float* features1 = (const float*)d_in[2];
    const float* features2 = (const float*)d_in[3];
    const float* w1 = (const float*)d_in[4];
    const float* b1 = (const float*)d_in[5];
    const float* g1 = (const float*)d_in[6];
    const float* be1 = (const float*)d_in[7];
    const float* m1 = (const float*)d_in[8];
    const float* v1 = (const float*)d_in[9];
    const float* w2 = (const float*)d_in[10];
    const float* b2 = (const float*)d_in[11];
    const float* g2 = (const float*)d_in[12];
    const float* be2 = (const float*)d_in[13];
    const float* m2 = (const float*)d_in[14];
    const float* v2 = (const float*)d_in[15];
    float* out = (float*)d_out;

    cudaFuncSetAttribute(mlp_fused_kernel,
                         cudaFuncAttributeMaxDynamicSharedMemorySize, MLP_SMEM);

    transpose_f2_kernel<<<dim3(N2_ / 32, C2_ / 32, B_), dim3(32, 8)>>>(features2);
    setup_kernel<<<96, 256>>>(xyz2, w1, b1, g1, be1, m1, v1,
                              w2, b2, g2, be2, m2, v2);
    knn_part_kernel<<<dim3(N1_ / 256, 4, B_), 128>>>(xyz1);
    knn_merge_kernel<<<(B_ * N1_) / 256, 256>>>(xyz1);
    interp_skip_kernel<<<4096 + 8192, 256>>>(features1);
    mlp_fused_kernel<<<B_ * (N1_ / 64), 256, MLP_SMEM>>>(out);
}

// round 8
// speedup vs baseline: 1.5001x; 1.5001x over previous
#include <cuda_runtime.h>
#include <cuda_fp16.h>
#include <cstdint>

// Problem constants
#define B_   8
#define N1_  8192
#define N2_  2048
#define C1_  128
#define C2_  256
#define H_   256
#define CIN_ 384   // C2 + C1

// ---------------- device scratch (no allocations allowed) ----------------
__device__ float  g_feat2t[B_ * N2_ * C2_];     // [B][N2][C2] fp32
__device__ float4 g_x2p[B_ * N2_];              // packed {x,y,z,|x|^2}
__device__ int    g_idx[B_ * N1_ * 3];
__device__ float  g_w  [B_ * N1_ * 3];
__device__ float  g_pd [B_ * N1_ * 4 * 3];      // partial top-3 dists
__device__ int    g_pi [B_ * N1_ * 4 * 3];      // partial top-3 indices
__device__ __half g_xcat[B_ * N1_ * CIN_];      // [B][N1][384] fp16
__device__ __half g_A1h[H_ * CIN_];             // fp16 folded weights
__device__ float  g_c1[H_];
__device__ __half g_A2h[H_ * H_];
__device__ float  g_c2[H_];

// ---------------- small PTX helpers ----------------------------------------
__device__ __forceinline__ uint32_t smem_u32(const void* p) {
    uint32_t a;
    asm("{ .reg .u64 t; cvta.to.shared.u64 t, %1; cvt.u32.u64 %0, t; }" : "=r"(a) : "l"(p));
    return a;
}
__device__ __forceinline__ void cpa16(uint32_t dst, const void* src) {
    asm volatile("cp.async.cg.shared.global [%0], [%1], 16;" :: "r"(dst), "l"(src));
}
#define CP_COMMIT()  asm volatile("cp.async.commit_group;")
#define CP_WAIT1()   asm volatile("cp.async.wait_group 1;")
#define CP_WAIT0()   asm volatile("cp.async.wait_group 0;")

// m16n8k16 fp16 MMA, fp32 accum, D = A*B + D
__device__ __forceinline__ void mma_f16(float* c, const uint32_t* a,
                                        uint32_t b0, uint32_t b1) {
    asm volatile(
        "mma.sync.aligned.m16n8k16.row.col.f32.f16.f16.f32 "
        "{%0,%1,%2,%3}, {%4,%5,%6,%7}, {%8,%9}, {%0,%1,%2,%3};"
        : "+f"(c[0]), "+f"(c[1]), "+f"(c[2]), "+f"(c[3])
        : "r"(a[0]), "r"(a[1]), "r"(a[2]), "r"(a[3]), "r"(b0), "r"(b1));
}
__device__ __forceinline__ uint32_t pack_h2(float lo, float hi) {
    __half2 h = __floats2half2_rn(lo, hi);
    return *(uint32_t*)&h;
}

// ---------------- 1) transpose features2 [B][C2][N2] -> [B][N2][C2] --------
__global__ void transpose_f2_kernel(const float* __restrict__ f2) {
    __shared__ float tile[32][33];
    int b  = blockIdx.z;
    int c0 = blockIdx.y * 32;
    int n0 = blockIdx.x * 32;
    int tx = threadIdx.x, ty = threadIdx.y;
    const float* src = f2 + (size_t)b * C2_ * N2_;
#pragma unroll
    for (int i = 0; i < 32; i += 8)
        tile[ty + i][tx] = src[(size_t)(c0 + ty + i) * N2_ + n0 + tx];
    __syncthreads();
    float* dst = g_feat2t + (size_t)b * N2_ * C2_;
#pragma unroll
    for (int i = 0; i < 32; i += 8)
        dst[(size_t)(n0 + ty + i) * C2_ + c0 + tx] = tile[tx][ty + i];
}

// ---------------- 2) setup: pack xyz2 + fold BN into fp16 weights ----------
__global__ void setup_kernel(const float* __restrict__ xyz2,
                             const float* __restrict__ w1, const float* __restrict__ b1,
                             const float* __restrict__ g1, const float* __restrict__ be1,
                             const float* __restrict__ m1, const float* __restrict__ v1,
                             const float* __restrict__ w2, const float* __restrict__ b2,
                             const float* __restrict__ g2, const float* __restrict__ be2,
                             const float* __restrict__ m2, const float* __restrict__ v2) {
    int blk = blockIdx.x;
    int t = threadIdx.x;
    if (blk < 64) {                       // pack xyz2
        int b = blk >> 3;
        int i = (blk & 7) * 256 + t;
        const float* x2 = xyz2 + (size_t)b * 3 * N2_;
        float X = x2[i], Y = x2[N2_ + i], Z = x2[2 * N2_ + i];
        g_x2p[b * N2_ + i] = make_float4(X, Y, Z, X * X + Y * Y + Z * Z);
    } else {                              // fold BN
        int tid2 = (blk - 64) * 256 + t;
        if (tid2 < H_) {
            float s1 = g1[tid2] * rsqrtf(v1[tid2] + 1e-5f);
            g_c1[tid2] = (b1[tid2] - m1[tid2]) * s1 + be1[tid2];
            float s2 = g2[tid2] * rsqrtf(v2[tid2] + 1e-5f);
            g_c2[tid2] = (b2[tid2] - m2[tid2]) * s2 + be2[tid2];
        }
        for (int j = tid2; j < H_ * CIN_; j += 8192) {
            int o = j / CIN_;
            float s = g1[o] * rsqrtf(v1[o] + 1e-5f);
            g_A1h[j] = __float2half_rn(w1[j] * s);
        }
        for (int j = tid2; j < H_ * H_; j += 8192) {
            int o = j / H_;
            float s = g2[o] * rsqrtf(v2[o] + 1e-5f);
            g_A2h[j] = __float2half_rn(w2[j] * s);
        }
    }
}

// ---------------- 3) kNN partial: quarter of N2, 2 points/thread -----------
#define QN_ (N2_ / 4)   // 512
__global__ void __launch_bounds__(128)
knn_part_kernel(const float* __restrict__ xyz1) {
    __shared__ float4 s2[QN_];
    int b  = blockIdx.z;
    int q  = blockIdx.y;
    int n0 = blockIdx.x * 256;
    int t  = threadIdx.x;

    const float4* src = g_x2p + b * N2_ + q * QN_;
    for (int i = t; i < QN_; i += 128) s2[i] = src[i];
    __syncthreads();

    const float* x1 = xyz1 + (size_t)b * 3 * N1_;
    int na = n0 + t, nb = n0 + 128 + t;
    float ax = x1[na], ay = x1[N1_ + na], az = x1[2 * N1_ + na];
    float bx = x1[nb], by = x1[N1_ + nb], bz = x1[2 * N1_ + nb];

    float ad0 = 3.4e38f, ad1 = 3.4e38f, ad2 = 3.4e38f;
    float bd0 = 3.4e38f, bd1 = 3.4e38f, bd2 = 3.4e38f;
    int ai0 = 0, ai1 = 0, ai2 = 0, bi0 = 0, bi1 = 0, bi2 = 0;

#pragma unroll 4
    for (int j = 0; j < QN_; j++) {
        float4 p = s2[j];
        float ta = ax * p.x; ta = fmaf(ay, p.y, ta); ta = fmaf(az, p.z, ta);
        float da = fmaf(-2.0f, ta, p.w);
        float tb = bx * p.x; tb = fmaf(by, p.y, tb); tb = fmaf(bz, p.z, tb);
        float db = fmaf(-2.0f, tb, p.w);
        if (da < ad2) {
            if (da < ad1) {
                if (da < ad0) { ad2 = ad1; ai2 = ai1; ad1 = ad0; ai1 = ai0; ad0 = da; ai0 = j; }
                else          { ad2 = ad1; ai2 = ai1; ad1 = da;  ai1 = j; }
            } else            { ad2 = da;  ai2 = j; }
        }
        if (db < bd2) {
            if (db < bd1) {
                if (db < bd0) { bd2 = bd1; bi2 = bi1; bd1 = bd0; bi1 = bi0; bd0 = db; bi0 = j; }
                else          { bd2 = bd1; bi2 = bi1; bd1 = db;  bi1 = j; }
            } else            { bd2 = db;  bi2 = j; }
        }
    }
    int joff = q * QN_;
    size_t basea = ((size_t)(b * N1_ + na) * 4 + q) * 3;
    g_pd[basea + 0] = ad0; g_pd[basea + 1] = ad1; g_pd[basea + 2] = ad2;
    g_pi[basea + 0] = ai0 + joff; g_pi[basea + 1] = ai1 + joff; g_pi[basea + 2] = ai2 + joff;
    size_t baseb = ((size_t)(b * N1_ + nb) * 4 + q) * 3;
    g_pd[baseb + 0] = bd0; g_pd[baseb + 1] = bd1; g_pd[baseb + 2] = bd2;
    g_pi[baseb + 0] = bi0 + joff; g_pi[baseb + 1] = bi1 + joff; g_pi[baseb + 2] = bi2 + joff;
}

// ---------------- 4) merge 4 partial top-3 lists + weights -----------------
__global__ void knn_merge_kernel(const float* __restrict__ xyz1) {
    int gid = blockIdx.x * 256 + threadIdx.x;
    int b = gid >> 13;
    int n = gid & (N1_ - 1);

    float d0 = 3.4e38f, d1 = 3.4e38f, d2 = 3.4e38f;
    int   i0 = 0, i1 = 0, i2 = 0;
    size_t base = (size_t)gid * 12;
#pragma unroll
    for (int k = 0; k < 12; k++) {
        float d = g_pd[base + k];
        int   i = g_pi[base + k];
        if (d < d2) {
            if (d < d1) {
                if (d < d0) { d2 = d1; i2 = i1; d1 = d0; i1 = i0; d0 = d; i0 = i; }
                else        { d2 = d1; i2 = i1; d1 = d;  i1 = i; }
            } else          { d2 = d;  i2 = i; }
        }
    }
    const float* x1 = xyz1 + (size_t)b * 3 * N1_;
    float px = x1[n], py = x1[N1_ + n], pz = x1[2 * N1_ + n];
    float pn = px * px + py * py + pz * pz;
    d0 = fmaxf(d0 + pn, 1e-10f);
    d1 = fmaxf(d1 + pn, 1e-10f);
    d2 = fmaxf(d2 + pn, 1e-10f);
    float w0 = 1.0f / d0, w1 = 1.0f / d1, w2 = 1.0f / d2;
    float inv = 1.0f / (w0 + w1 + w2);
    size_t ob = (size_t)gid * 3;
    g_idx[ob + 0] = i0; g_idx[ob + 1] = i1; g_idx[ob + 2] = i2;
    g_w[ob + 0] = w0 * inv; g_w[ob + 1] = w1 * inv; g_w[ob + 2] = w2 * inv;
}

// ---------------- 5) interp (ch 0..255) + skip transpose (ch 256..383) -----
__global__ void interp_skip_kernel(const float* __restrict__ f1) {
    __shared__ int   sidx[16 * 3];
    __shared__ float swt [16 * 3];
    __shared__ float tile[32][33];
    int blk = blockIdx.x;
    int t = threadIdx.x;
    if (blk < 4096) {
        int b  = blk >> 9;
        int n0 = (blk & 511) * 16;
        if (t < 48) {
            size_t base = ((size_t)(b * N1_ + n0)) * 3;
            sidx[t] = g_idx[base + t];
            swt[t]  = g_w[base + t];
        }
        __syncthreads();
        const float* f2 = g_feat2t + (size_t)b * N2_ * C2_;
        __half* xc = g_xcat + ((size_t)(b * N1_ + n0)) * CIN_ + t;
#pragma unroll 4
        for (int p = 0; p < 16; p++) {
            float acc = swt[p * 3 + 0] * f2[(size_t)sidx[p * 3 + 0] * C2_ + t]
                      + swt[p * 3 + 1] * f2[(size_t)sidx[p * 3 + 1] * C2_ + t]
                      + swt[p * 3 + 2] * f2[(size_t)sidx[p * 3 + 2] * C2_ + t];
            xc[(size_t)p * CIN_] = __float2half_rn(acc);
        }
    } else {
        int r  = blk - 4096;
        int b  = r >> 10;
        int rem = r & 1023;
        int c0 = (rem >> 8) * 32;
        int n0 = (rem & 255) * 32;
        int tx = t & 31, ty = t >> 5;
        const float* src = f1 + (size_t)b * C1_ * N1_;
#pragma unroll
        for (int i = 0; i < 32; i += 8)
            tile[ty + i][tx] = src[(size_t)(c0 + ty + i) * N1_ + n0 + tx];
        __syncthreads();
        __half* dst = g_xcat + (size_t)b * N1_ * CIN_;
#pragma unroll
        for (int i = 0; i < 32; i += 8)
            dst[(size_t)(n0 + ty + i) * CIN_ + C2_ + c0 + tx] =
                __float2half_rn(tile[tx][ty + i]);
    }
}

// ---------------- 6) fused 2-layer MLP via fp16 mma.sync -------------------
// Block: 128 points x 256 out-ch, 256 threads (8 warps: 2M x 4N, warp 64x64).
// fp16 m16n8k16, fp32 accum. Frag-ordered SMEM; yfrag holds layer-1 output
// as packed half2 directly in layer-2 A-fragment order.
// SMEM (u32 units): phase1 bufs 2x3072 [0,6144); phase2 W2 bufs 2x2048
// (reuse [0,4096)); yfrag [6144, 22528). Total 90112 bytes.
#define YF_OFF   6144
#define MLP_SMEM 90112
#define KT1 (CIN_ / 16)   // 24
#define KT2 (H_ / 16)     // 16

__global__ void __launch_bounds__(256)
mlp_fused_kernel(float* __restrict__ out_final) {
    extern __shared__ uint32_t smem[];
    uint32_t sbase = smem_u32(smem);

    int tid  = threadIdx.x;
    int wid  = tid >> 5;
    int lane = tid & 31;
    int g    = lane >> 2;        // groupID 0..7
    int t4   = lane & 3;         // threadID_in_group

    int wm = wid & 1;            // 0..1  (M warps, 64 rows)
    int wn = wid >> 1;           // 0..3  (N warps, 64 cols)

    int bz = blockIdx.x >> 6;
    int m0 = (blockIdx.x & 63) * 128;

    const __half* Abase = g_xcat + ((size_t)(bz * N1_ + m0)) * CIN_;
    uint32_t* yf = smem + YF_OFF;

    float acc[4][8][4] = {};

    // ---- phase-1 staging: A 128x16h (256 chunks, 1/thr), B 256x16h (512, 2/thr)
#define STAGE1(buf, kt) do {                                                   \
    uint32_t dbase = sbase + (buf) * 12288;                                    \
    {                                                                          \
        int m = tid >> 1, c4 = tid & 1;                                        \
        int off = (((m >> 4) * 4) + 2 * c4 + ((m >> 3) & 1)) * 32 + (m & 7) * 4; \
        cpa16(dbase + off * 4, Abase + (size_t)m * CIN_ + (kt) * 16 + c4 * 8); \
    }                                                                          \
    _Pragma("unroll")                                                          \
    for (int c = 0; c < 2; c++) {                                              \
        int id = tid + c * 256;                                                \
        int n = id >> 1, c4 = id & 1;                                          \
        int off = 1024 + ((n >> 3) * 2 + c4) * 32 + (n & 7) * 4;               \
        cpa16(dbase + off * 4, g_A1h + (size_t)n * CIN_ + (kt) * 16 + c4 * 8); \
    }                                                                          \
    CP_COMMIT();                                                               \
} while (0)

#define STAGE2B(buf, kt) do {                                                  \
    uint32_t dbase = sbase + (buf) * 8192;                                     \
    _Pragma("unroll")                                                          \
    for (int c = 0; c < 2; c++) {                                              \
        int id = tid + c * 256;                                                \
        int n = id >> 1, c4 = id & 1;                                          \
        int off = ((n >> 3) * 2 + c4) * 32 + (n & 7) * 4;                      \
        cpa16(dbase + off * 4, g_A2h + (size_t)n * H_ + (kt) * 16 + c4 * 8);   \
    }                                                                          \
    CP_COMMIT();                                                               \
} while (0)

    // ================= phase 1: K = 384, 24 k16-tiles =================
    STAGE1(0, 0);
#pragma unroll 1
    for (int kt = 0; kt < KT1; kt++) {
        int cur = kt & 1;
        if (kt + 1 < KT1) { STAGE1(cur ^ 1, kt + 1); CP_WAIT1(); }
        else              { CP_WAIT0(); }
        __syncthreads();
        const uint32_t* As = smem + cur * 3072;
        const uint32_t* Bs = As + 1024;
        uint32_t a[4][4];
#pragma unroll
        for (int mi = 0; mi < 4; mi++) {
            const uint32_t* ap = As + ((wm * 4 + mi) * 4) * 32 + lane;
            a[mi][0] = ap[0];
            a[mi][1] = ap[32];
            a[mi][2] = ap[64];
            a[mi][3] = ap[96];
        }
#pragma unroll
        for (int ni = 0; ni < 8; ni++) {
            const uint32_t* bp = Bs + ((wn * 8 + ni) * 2) * 32 + lane;
            uint32_t b0 = bp[0];
            uint32_t b1 = bp[32];
#pragma unroll
            for (int mi = 0; mi < 4; mi++)
                mma_f16(acc[mi][ni], a[mi], b0, b1);
        }
        __syncthreads();
    }

    STAGE2B(0, 0);   // overlap W2 k-tile 0 with epilogue-1

    // ---- epilogue 1: bias+relu -> yfrag (phase-2 A-frag order, half2) ----
#pragma unroll
    for (int ni = 0; ni < 8; ni++) {
        int nch = wn * 64 + ni * 8 + 2 * t4;
        float bv0 = __ldg(&g_c1[nch]);
        float bv1 = __ldg(&g_c1[nch + 1]);
        int kt = wn * 4 + (ni >> 1);
        int rb = 2 * (ni & 1);
#pragma unroll
        for (int mi = 0; mi < 4; mi++) {
            int mt = wm * 4 + mi;
            float c0 = fmaxf(acc[mi][ni][0] + bv0, 0.0f);
            float c1 = fmaxf(acc[mi][ni][1] + bv1, 0.0f);
            float c2 = fmaxf(acc[mi][ni][2] + bv0, 0.0f);
            float c3 = fmaxf(acc[mi][ni][3] + bv1, 0.0f);
            yf[((mt * 16 + kt) * 4 + rb) * 32 + lane]     = pack_h2(c0, c1);
            yf[((mt * 16 + kt) * 4 + rb + 1) * 32 + lane] = pack_h2(c2, c3);
        }
    }

    // re-zero accumulators
#pragma unroll
    for (int mi = 0; mi < 4; mi++)
#pragma unroll
        for (int ni = 0; ni < 8; ni++)
#pragma unroll
            for (int j = 0; j < 4; j++) acc[mi][ni][j] = 0.0f;

    __syncthreads();   // yfrag visible to all

    // ================= phase 2: K = 256, A resident in yfrag =================
#pragma unroll 1
    for (int kt = 0; kt < KT2; kt++) {
        int cur = kt & 1;
        if (kt + 1 < KT2) { STAGE2B(cur ^ 1, kt + 1); CP_WAIT1(); }
        else              { CP_WAIT0(); }
        __syncthreads();
        const uint32_t* Bs = smem + cur * 2048;
        uint32_t a[4][4];
#pragma unroll
        for (int mi = 0; mi < 4; mi++) {
            const uint32_t* ap = yf + (((wm * 4 + mi) * 16 + kt) * 4) * 32 + lane;
            a[mi][0] = ap[0];
            a[mi][1] = ap[32];
            a[mi][2] = ap[64];
            a[mi][3] = ap[96];
        }
#pragma unroll
        for (int ni = 0; ni < 8; ni++) {
            const uint32_t* bp = Bs + ((wn * 8 + ni) * 2) * 32 + lane;
            uint32_t b0 = bp[0];
            uint32_t b1 = bp[32];
#pragma unroll
            for (int mi = 0; mi < 4; mi++)
                mma_f16(acc[mi][ni], a[mi], b0, b1);
        }
        __syncthreads();
    }

    // ---- epilogue 2: bias+relu -> out [B][H][N1] (coalesced along points) ----
    float* dst = out_final + (size_t)bz * H_ * N1_;
#pragma unroll
    for (int ni = 0; ni < 8; ni++) {
        int n = wn * 64 + ni * 8 + 2 * t4;
        float bv0 = __ldg(&g_c2[n]);
        float bv1 = __ldg(&g_c2[n + 1]);
#pragma unroll
        for (int mi = 0; mi < 4; mi++) {
            int m = m0 + wm * 64 + mi * 16 + g;
            float c0 = fmaxf(acc[mi][ni][0] + bv0, 0.0f);
            float c1 = fmaxf(acc[mi][ni][1] + bv1, 0.0f);
            float c2 = fmaxf(acc[mi][ni][2] + bv0, 0.0f);
            float c3 = fmaxf(acc[mi][ni][3] + bv1, 0.0f);
            dst[(size_t)n * N1_ + m]           = c0;
            dst[(size_t)(n + 1) * N1_ + m]     = c1;
            dst[(size_t)n * N1_ + m + 8]       = c2;
            dst[(size_t)(n + 1) * N1_ + m + 8] = c3;
        }
    }
}

// ---------------- launch ----------------------------------------------------
extern "C" void kernel_launch(void* const* d_in, const int* in_sizes, int n_in,
                              void* d_out, int out_size) {
    const float* xyz1      = (const float*)d_in[0];
    const float* xyz2      = (const float*)d_in[1];
    const float* features1 = (const float*)d_in[2];
    const float* features2 = (const float*)d_in[3];
    const float* w1 = (const float*)d_in[4];
    const float* b1 = (const float*)d_in[5];
    const float* g1 = (const float*)d_in[6];
    const float* be1 = (const float*)d_in[7];
    const float* m1 = (const float*)d_in[8];
    const float* v1 = (const float*)d_in[9];
    const float* w2 = (const float*)d_in[10];
    const float* b2 = (const float*)d_in[11];
    const float* g2 = (const float*)d_in[12];
    const float* be2 = (const float*)d_in[13];
    const float* m2 = (const float*)d_in[14];
    const float* v2 = (const float*)d_in[15];
    float* out = (float*)d_out;

    cudaFuncSetAttribute(mlp_fused_kernel,
                         cudaFuncAttributeMaxDynamicSharedMemorySize, MLP_SMEM);

    transpose_f2_kernel<<<dim3(N2_ / 32, C2_ / 32, B_), dim3(32, 8)>>>(features2);
    setup_kernel<<<96, 256>>>(xyz2, w1, b1, g1, be1, m1, v1,
                              w2, b2, g2, be2, m2, v2);
    knn_part_kernel<<<dim3(N1_ / 256, 4, B_), 128>>>(xyz1);
    knn_merge_kernel<<<(B_ * N1_) / 256, 256>>>(xyz1);
    interp_skip_kernel<<<4096 + 8192, 256>>>(features1);
    mlp_fused_kernel<<<512, 256, MLP_SMEM>>>(out);
}